// round 7
// baseline (speedup 1.0000x reference)
#include <cuda_runtime.h>
#include <cuda_bf16.h>
#include <cstdint>

// ROI mean-pool, v7: cp.async double-buffered pipeline over 8 planes per CTA.
// fmap:  [B=64, C=256, H=80, W=80] f32   boxes: [B=64, N=100, 4]   out: [B,N,C]

#define Bn     64
#define Cn     256
#define Hn     80
#define Wn     80
#define Nn     100
#define PLANES 8
#define PLANE_F4 ((Hn * Wn) / 4)          // 1600 float4 per plane
#define BUF_FLOATS (Hn * Wn)              // 6400

__device__ __forceinline__ void cp_async16(uint32_t dst, const void* src) {
    asm volatile("cp.async.cg.shared.global [%0], [%1], 16;" :: "r"(dst), "l"(src));
}
__device__ __forceinline__ void cp_commit() {
    asm volatile("cp.async.commit_group;");
}
template <int N>
__device__ __forceinline__ void cp_wait() {
    asm volatile("cp.async.wait_group %0;" :: "n"(N));
}

__global__ __launch_bounds__(256)
void roi_pool_v7_kernel(const float* __restrict__ fmap,
                        const float* __restrict__ boxes,
                        float* __restrict__ out)
{
    // dynamic smem: buf0[6400] | buf1[6400] | zrow[80] | BC[100] int4
    extern __shared__ __align__(16) float S[];
    float* zrow = S + 2 * BUF_FLOATS;
    int4*  BC   = reinterpret_cast<int4*>(S + 2 * BUF_FLOATS + Wn);

    const int p0  = blockIdx.x * PLANES;   // 8 consecutive planes, same b
    const int b   = p0 >> 8;
    const int c0  = p0 & 255;
    const int tid = threadIdx.x;
    const uint32_t sbase = (uint32_t)__cvta_generic_to_shared(S);

    // Prologue: kick off plane 0 load (async, L1-bypass).
    {
        const float4* g = reinterpret_cast<const float4*>(fmap + (size_t)p0 * BUF_FLOATS);
        for (int i = tid; i < PLANE_F4; i += 256)
            cp_async16(sbase + (uint32_t)i * 16u, g + i);
        cp_commit();
    }

    // Overlapped with the load: zero row + box-coord precompute.
    if (tid < Wn) zrow[tid] = 0.0f;
    if (tid < Nn) {
        float4 bb = reinterpret_cast<const float4*>(boxes + (size_t)b * (Nn * 4))[tid];
        // Match JAX exactly: IEEE div by 640, IEEE mul by 80, trunc, clip.
        int x1 = min(max((int)(__fmul_rn(__fdiv_rn(bb.x, 640.0f), 80.0f)), 0), Wn);
        int y1 = min(max((int)(__fmul_rn(__fdiv_rn(bb.y, 640.0f), 80.0f)), 0), Hn);
        int x2 = min(max((int)(__fmul_rn(__fdiv_rn(bb.z, 640.0f), 80.0f)), 0), Wn);
        int y2 = min(max((int)(__fmul_rn(__fdiv_rn(bb.w, 640.0f), 80.0f)), 0), Hn);
        BC[tid] = make_int4(x1, y1, x2, y2);
    }

    const int team = tid >> 3;             // 0..31
    const int tl   = tid & 7;

    #pragma unroll 1
    for (int k = 0; k < PLANES; ++k) {
        float* cur = S + (k & 1) * BUF_FLOATS;

        // Issue next plane's load, then wait for the current plane's group.
        if (k + 1 < PLANES) {
            const float4* g = reinterpret_cast<const float4*>(
                fmap + (size_t)(p0 + k + 1) * BUF_FLOATS);
            const uint32_t doff = ((k + 1) & 1) * (BUF_FLOATS * 4u);
            for (int i = tid; i < PLANE_F4; i += 256)
                cp_async16(sbase + doff + (uint32_t)i * 16u, g + i);
            cp_commit();
            cp_wait<1>();                  // plane k complete (k+1 may be pending)
        } else {
            cp_wait<0>();
        }
        __syncthreads();

        // Split in-place column scan (160 threads, 40-deep chains).
        // rows 0..39 -> true prefix C[1..40]; rows 40..79 -> local prefix.
        if (tid < 160) {
            const int col  = (tid < Wn) ? tid : tid - Wn;
            const int rowb = (tid < Wn) ? 0 : 40;
            float* d = cur + rowb * Wn + col;
            float acc = 0.0f;
            #pragma unroll 8
            for (int i = 0; i < 40; ++i) {
                acc += d[i * Wn];
                d[i * Wn] = acc;
            }
        }
        __syncthreads();

        // Box phase: 8-lane team per box; straddling boxes add C[40] row.
        float* __restrict__ ob = out + (size_t)b * (Nn * Cn) + c0 + k;
        const float* __restrict__ trow = cur + 39 * Wn;   // C[40]

        for (int n = team; n < Nn; n += 32) {
            int4 q = BC[n];                // x1,y1,x2,y2
            const float* __restrict__ r2 = (q.w > 0) ? cur + (q.w - 1) * Wn : zrow;
            const float* __restrict__ r1 = (q.y > 0) ? cur + (q.y - 1) * Wn : zrow;
            const bool straddle = (q.y <= 40) && (q.w >= 41);

            float s = 0.0f;
            if (straddle) {
                for (int x = q.x + tl; x < q.z; x += 8)
                    s += r2[x] - r1[x] + trow[x];
            } else {
                for (int x = q.x + tl; x < q.z; x += 8)
                    s += r2[x] - r1[x];
            }
            // width-8 tree reduce; N%4==0 keeps warp-uniform trip validity.
            s += __shfl_down_sync(0xFFFFFFFFu, s, 4, 8);
            s += __shfl_down_sync(0xFFFFFFFFu, s, 2, 8);
            s += __shfl_down_sync(0xFFFFFFFFu, s, 1, 8);

            if (tl == 0) {
                int dy = q.w - q.y;
                int dx = q.z - q.x;
                bool valid = (dy > 0) && (dx > 0);
                int  area  = max(dy * dx, 1);
                ob[(size_t)n * Cn] = valid ? s / (float)area : 0.0f;
            }
        }
        __syncthreads();                   // cur is free for iteration k+2's load
    }
}

extern "C" void kernel_launch(void* const* d_in, const int* in_sizes, int n_in,
                              void* d_out, int out_size)
{
    const float* fmap  = (const float*)d_in[0];   // [64,256,80,80]
    const float* boxes = (const float*)d_in[1];   // [64,100,4]
    float*       out   = (float*)d_out;           // [64,100,256]

    (void)in_sizes; (void)n_in; (void)out_size;

    const int smem_bytes = (2 * BUF_FLOATS + Wn) * 4 + Nn * 16;   // 53,120 B
    cudaFuncSetAttribute(roi_pool_v7_kernel,
                         cudaFuncAttributeMaxDynamicSharedMemorySize, smem_bytes);

    roi_pool_v7_kernel<<<(Bn * Cn) / PLANES, 256, smem_bytes>>>(fmap, boxes, out);
}